// round 4
// baseline (speedup 1.0000x reference)
#include <cuda_runtime.h>
#include <cstdint>

#define VOCAB   50257
#define EMBED   512
#define HIDDEN  1024
#define TSTEPS  2048

// Scratch (allocation-free rule: __device__ globals)
__device__ float g_xp[TSTEPS * HIDDEN];   // 8 MB: input projections
__device__ float g_hs[TSTEPS * HIDDEN];   // 8 MB: hidden states per step
__device__ unsigned long long g_bar_cnt;  // monotonic grid-barrier counter (zero-init at load)

// ---------------------------------------------------------------------------
// SGEMM (NT): C[M,N] = A[M,K] @ B[N,K]^T (+ bias[N]).  A rows optionally
// gathered through idx (embedding lookup fused into the GEMM).
// 128x128 tile, BK=8, 8x8 register micro-tile, 256 threads.
// M, K assumed multiples of 128/8; N bounds-checked (VOCAB=50257).
// ---------------------------------------------------------------------------
template <bool GATHER>
__global__ __launch_bounds__(256, 2)
void sgemm_nt_kernel(const float* __restrict__ A,
                     const float* __restrict__ B,
                     const float* __restrict__ bias,
                     float* __restrict__ C,
                     const int* __restrict__ idx,
                     int M, int N, int K)
{
    const int BM = 128, BN = 128, BK = 8;
    __shared__ float As[BK][BM];
    __shared__ float Bs[BK][BN];

    const int tid  = threadIdx.x;          // 0..255
    const int row0 = blockIdx.y * BM;
    const int col0 = blockIdx.x * BN;

    // global->smem load mapping: each thread moves one float4 of A and one of B
    const int lr = tid >> 1;               // 0..127  (tile row)
    const int lc = (tid & 1) * 4;          // 0 or 4  (k offset)

    const int arow_g = row0 + lr;
    const float* Arow = A + (size_t)(GATHER ? idx[arow_g] : arow_g) * K;

    const int brow_g = col0 + lr;
    const float* Brow = B + (size_t)brow_g * K;
    const bool bvalid = (brow_g < N);

    const int tx = tid & 15;               // 0..15 -> 8 output cols each
    const int ty = tid >> 4;               // 0..15 -> 8 output rows each

    float acc[8][8];
#pragma unroll
    for (int i = 0; i < 8; i++)
#pragma unroll
        for (int j = 0; j < 8; j++) acc[i][j] = 0.0f;

    for (int k0 = 0; k0 < K; k0 += BK) {
        float4 av = *(const float4*)(Arow + k0 + lc);
        float4 bv = make_float4(0.f, 0.f, 0.f, 0.f);
        if (bvalid) bv = *(const float4*)(Brow + k0 + lc);

        As[lc + 0][lr] = av.x;
        As[lc + 1][lr] = av.y;
        As[lc + 2][lr] = av.z;
        As[lc + 3][lr] = av.w;
        Bs[lc + 0][lr] = bv.x;
        Bs[lc + 1][lr] = bv.y;
        Bs[lc + 2][lr] = bv.z;
        Bs[lc + 3][lr] = bv.w;
        __syncthreads();

#pragma unroll
        for (int k = 0; k < BK; k++) {
            float af[8], bf[8];
#pragma unroll
            for (int i = 0; i < 8; i++) af[i] = As[k][ty * 8 + i];
#pragma unroll
            for (int j = 0; j < 8; j++) bf[j] = Bs[k][tx * 8 + j];
#pragma unroll
            for (int i = 0; i < 8; i++)
#pragma unroll
                for (int j = 0; j < 8; j++) acc[i][j] += af[i] * bf[j];
        }
        __syncthreads();
    }

    // epilogue (scalar stores: N=50257 is odd, no alignment guarantee)
#pragma unroll
    for (int i = 0; i < 8; i++) {
        const int row = row0 + ty * 8 + i;
        float* Crow = C + (size_t)row * N;
#pragma unroll
        for (int j = 0; j < 8; j++) {
            const int col = col0 + tx * 8 + j;
            if (col < N) {
                float v = acc[i][j];
                if (bias) v += bias[col];
                Crow[col] = v;
            }
        }
    }
}

// ---------------------------------------------------------------------------
// Recurrence: h_t = tanh(xp_t + W_hh @ h_{t-1} + b_hh), t = 0..2047.
// Persistent kernel: 64 blocks x 512 threads (16 warps). Warp w of block b
// owns row (b*16 + w). Its 1024 W_hh values live in 32 regs/lane for the
// whole launch. Per step: h_{t-1} staged in smem, 32 FMAs/lane, warp
// reduction, tanh, write h_t, then a grid-wide barrier.
//
// Barrier: monotonic 64-bit counter. Each launch consumes exactly
// TSTEPS*NB tickets; the launch-base is the first ticket rounded down to a
// multiple of TSTEPS*NB, so it is replay-safe across CUDA-graph replays
// with no reset and no sense-reversal race.
// ---------------------------------------------------------------------------
#define RNN_NB 64
#define RNN_NT 512

__global__ __launch_bounds__(RNN_NT, 1)
void rnn_recurrence_kernel(const float* __restrict__ xp,
                           const float* __restrict__ W_hh,
                           const float* __restrict__ b_hh,
                           float* __restrict__ hs,
                           float* __restrict__ h_final)
{
    __shared__ float hsm[HIDDEN];

    const int tid  = threadIdx.x;
    const int warp = tid >> 5;
    const int lane = tid & 31;
    const int row  = blockIdx.x * 16 + warp;   // 64*16 = 1024 rows

    // W_hh row slice -> registers (lane handles cols lane, lane+32, ...)
    float w[32];
    const float* Wrow = W_hh + (size_t)row * HIDDEN;
#pragma unroll
    for (int k = 0; k < 32; k++) w[k] = Wrow[lane + 32 * k];
    const float bias = b_hh[row];

    const unsigned long long TOTAL = (unsigned long long)TSTEPS * RNN_NB;
    unsigned long long base = 0;   // meaningful only in tid==0

    for (int t = 0; t < TSTEPS; t++) {
        // stage h_{t-1}
        if (t == 0) {
            hsm[tid]       = 0.0f;
            hsm[tid + 512] = 0.0f;
        } else {
            const float* hprev = hs + (size_t)(t - 1) * HIDDEN;
            hsm[tid]       = hprev[tid];
            hsm[tid + 512] = hprev[tid + 512];
        }
        __syncthreads();

        float acc = 0.0f;
#pragma unroll
        for (int k = 0; k < 32; k++) acc += w[k] * hsm[lane + 32 * k];
#pragma unroll
        for (int off = 16; off > 0; off >>= 1)
            acc += __shfl_down_sync(0xffffffffu, acc, off);

        if (lane == 0) {
            float v = tanhf(acc + xp[(size_t)t * HIDDEN + row] + bias);
            hs[(size_t)t * HIDDEN + row] = v;
            if (t == TSTEPS - 1) h_final[row] = v;
        }
        __syncthreads();              // all smem reads done; writes issued

        // ---- grid barrier ----
        if (tid == 0) {
            __threadfence();          // publish this block's hs[t] writes
            unsigned long long tk = atomicAdd(&g_bar_cnt, 1ULL);
            if (t == 0) base = (tk / TOTAL) * TOTAL;
            const unsigned long long target =
                base + (unsigned long long)(t + 1) * RNN_NB;
            while (*(volatile unsigned long long*)&g_bar_cnt < target) { }
            __threadfence();          // acquire peers' hs[t] writes
        }
        __syncthreads();
    }
}

// ---------------------------------------------------------------------------
// launch
// ---------------------------------------------------------------------------
extern "C" void kernel_launch(void* const* d_in, const int* in_sizes, int n_in,
                              void* d_out, int out_size)
{
    const int*   x     = (const int*)  d_in[0];   // [T]
    const float* emb   = (const float*)d_in[1];   // [VOCAB, EMBED]
    const float* W_xh  = (const float*)d_in[2];   // [HIDDEN, EMBED]
    const float* W_hh  = (const float*)d_in[3];   // [HIDDEN, HIDDEN]
    const float* b_hh  = (const float*)d_in[4];   // [HIDDEN]
    const float* W_out = (const float*)d_in[5];   // [VOCAB, HIDDEN]
    const float* b_out = (const float*)d_in[6];   // [VOCAB]

    float* logits  = (float*)d_out;                          // [T, VOCAB]
    float* h_final = (float*)d_out + (size_t)TSTEPS * VOCAB; // [HIDDEN]

    float* xp = nullptr;
    float* hs = nullptr;
    cudaGetSymbolAddress((void**)&xp, g_xp);
    cudaGetSymbolAddress((void**)&hs, g_hs);

    // 1) xp = emb[x] @ W_xh^T      (M=2048, N=1024, K=512)
    {
        dim3 grid(HIDDEN / 128, TSTEPS / 128);
        sgemm_nt_kernel<true><<<grid, 256>>>(emb, W_xh, nullptr, xp, x,
                                             TSTEPS, HIDDEN, EMBED);
    }

    // 2) sequential recurrence -> hs, h_final
    rnn_recurrence_kernel<<<RNN_NB, RNN_NT>>>(xp, W_hh, b_hh, hs, h_final);

    // 3) logits = hs @ W_out^T + b_out   (M=2048, N=50257, K=1024)
    {
        dim3 grid((VOCAB + 127) / 128, TSTEPS / 128);
        sgemm_nt_kernel<false><<<grid, 256>>>(hs, W_out, b_out, logits, nullptr,
                                              TSTEPS, VOCAB, HIDDEN);
    }
}

// round 11
// speedup vs baseline: 1.4211x; 1.4211x over previous
#include <cuda_runtime.h>
#include <cuda_bf16.h>
#include <cstdint>

#define VOCAB   50257
#define EMBED   512
#define HIDDEN  1024
#define TSTEPS  2048

// Scratch (allocation-free rule: __device__ globals)
__device__ float g_xp[TSTEPS * HIDDEN];   // 8 MB: input projections
__device__ float g_hs[TSTEPS * HIDDEN];   // 8 MB: hidden states per step
__device__ unsigned long long g_bar_cnt;  // monotonic grid-barrier counter

// ===========================================================================
// helpers
// ===========================================================================
__device__ __forceinline__ uint32_t smem_u32(const void* p) {
    uint32_t a;
    asm("{ .reg .u64 t; cvta.to.shared.u64 t, %1; cvt.u32.u64 %0, t; }"
        : "=r"(a) : "l"(p));
    return a;
}

// pack two fp32 -> bf16x2 (first arg -> low half)
__device__ __forceinline__ uint32_t pack_bf16x2(float lo, float hi) {
    uint32_t r;
    asm("cvt.rn.bf16x2.f32 %0, %1, %2;" : "=r"(r) : "f"(hi), "f"(lo));
    return r;
}
// split float4 into hi (bf16 round) and lo (bf16 of residual)
__device__ __forceinline__ void split4(float4 v, uint2& hi, uint2& lo) {
    uint32_t h0 = pack_bf16x2(v.x, v.y);
    uint32_t h1 = pack_bf16x2(v.z, v.w);
    float fx = __uint_as_float(h0 << 16);
    float fy = __uint_as_float(h0 & 0xFFFF0000u);
    float fz = __uint_as_float(h1 << 16);
    float fw = __uint_as_float(h1 & 0xFFFF0000u);
    uint32_t l0 = pack_bf16x2(v.x - fx, v.y - fy);
    uint32_t l1 = pack_bf16x2(v.z - fz, v.w - fw);
    hi = make_uint2(h0, h1);
    lo = make_uint2(l0, l1);
}

#define LDSM_X4(r0, r1, r2, r3, addr)                                       \
    asm volatile("ldmatrix.sync.aligned.m8n8.x4.shared.b16 {%0,%1,%2,%3}, [%4];" \
                 : "=r"(r0), "=r"(r1), "=r"(r2), "=r"(r3) : "r"(addr))

#define MMA_BF16(c, a0, a1, a2, a3, b0, b1)                                 \
    asm volatile("mma.sync.aligned.m16n8k16.row.col.f32.bf16.bf16.f32 "     \
                 "{%0,%1,%2,%3}, {%4,%5,%6,%7}, {%8,%9}, {%0,%1,%2,%3};"    \
                 : "+f"((c)[0]), "+f"((c)[1]), "+f"((c)[2]), "+f"((c)[3])   \
                 : "r"(a0), "r"(a1), "r"(a2), "r"(a3), "r"(b0), "r"(b1))

// ===========================================================================
// fp32 SGEMM (NT) — used only for the small xp = emb[x] @ W_xh^T GEMM
// ===========================================================================
template <bool GATHER>
__global__ __launch_bounds__(256, 2)
void sgemm_nt_kernel(const float* __restrict__ A,
                     const float* __restrict__ B,
                     const float* __restrict__ bias,
                     float* __restrict__ C,
                     const int* __restrict__ idx,
                     int M, int N, int K)
{
    const int BM = 128, BN = 128, BK = 8;
    __shared__ float As[BK][BM];
    __shared__ float Bs[BK][BN];

    const int tid  = threadIdx.x;
    const int row0 = blockIdx.y * BM;
    const int col0 = blockIdx.x * BN;

    const int lr = tid >> 1;
    const int lc = (tid & 1) * 4;

    const int arow_g = row0 + lr;
    const float* Arow = A + (size_t)(GATHER ? idx[arow_g] : arow_g) * K;

    const int brow_g = col0 + lr;
    const float* Brow = B + (size_t)brow_g * K;
    const bool bvalid = (brow_g < N);

    const int tx = tid & 15;
    const int ty = tid >> 4;

    float acc[8][8];
#pragma unroll
    for (int i = 0; i < 8; i++)
#pragma unroll
        for (int j = 0; j < 8; j++) acc[i][j] = 0.0f;

    for (int k0 = 0; k0 < K; k0 += BK) {
        float4 av = *(const float4*)(Arow + k0 + lc);
        float4 bv = make_float4(0.f, 0.f, 0.f, 0.f);
        if (bvalid) bv = *(const float4*)(Brow + k0 + lc);

        As[lc + 0][lr] = av.x; As[lc + 1][lr] = av.y;
        As[lc + 2][lr] = av.z; As[lc + 3][lr] = av.w;
        Bs[lc + 0][lr] = bv.x; Bs[lc + 1][lr] = bv.y;
        Bs[lc + 2][lr] = bv.z; Bs[lc + 3][lr] = bv.w;
        __syncthreads();

#pragma unroll
        for (int k = 0; k < BK; k++) {
            float af[8], bf[8];
#pragma unroll
            for (int i = 0; i < 8; i++) af[i] = As[k][ty * 8 + i];
#pragma unroll
            for (int j = 0; j < 8; j++) bf[j] = Bs[k][tx * 8 + j];
#pragma unroll
            for (int i = 0; i < 8; i++)
#pragma unroll
                for (int j = 0; j < 8; j++) acc[i][j] += af[i] * bf[j];
        }
        __syncthreads();
    }

#pragma unroll
    for (int i = 0; i < 8; i++) {
        const int row = row0 + ty * 8 + i;
        float* Crow = C + (size_t)row * N;
#pragma unroll
        for (int j = 0; j < 8; j++) {
            const int col = col0 + tx * 8 + j;
            if (col < N) {
                float v = acc[i][j];
                if (bias) v += bias[col];
                Crow[col] = v;
            }
        }
    }
}

// ===========================================================================
// Recurrence (unchanged): persistent kernel, W_hh rows in registers,
// replay-safe monotonic grid barrier.
// ===========================================================================
#define RNN_NB 64
#define RNN_NT 512

__global__ __launch_bounds__(RNN_NT, 1)
void rnn_recurrence_kernel(const float* __restrict__ xp,
                           const float* __restrict__ W_hh,
                           const float* __restrict__ b_hh,
                           float* __restrict__ hs,
                           float* __restrict__ h_final)
{
    __shared__ float hsm[HIDDEN];

    const int tid  = threadIdx.x;
    const int warp = tid >> 5;
    const int lane = tid & 31;
    const int row  = blockIdx.x * 16 + warp;

    float w[32];
    const float* Wrow = W_hh + (size_t)row * HIDDEN;
#pragma unroll
    for (int k = 0; k < 32; k++) w[k] = Wrow[lane + 32 * k];
    const float bias = b_hh[row];

    const unsigned long long TOTAL = (unsigned long long)TSTEPS * RNN_NB;
    unsigned long long base = 0;

    for (int t = 0; t < TSTEPS; t++) {
        if (t == 0) {
            hsm[tid]       = 0.0f;
            hsm[tid + 512] = 0.0f;
        } else {
            const float* hprev = hs + (size_t)(t - 1) * HIDDEN;
            hsm[tid]       = hprev[tid];
            hsm[tid + 512] = hprev[tid + 512];
        }
        __syncthreads();

        float acc = 0.0f;
#pragma unroll
        for (int k = 0; k < 32; k++) acc += w[k] * hsm[lane + 32 * k];
#pragma unroll
        for (int off = 16; off > 0; off >>= 1)
            acc += __shfl_down_sync(0xffffffffu, acc, off);

        if (lane == 0) {
            float v = tanhf(acc + xp[(size_t)t * HIDDEN + row] + bias);
            hs[(size_t)t * HIDDEN + row] = v;
            if (t == TSTEPS - 1) h_final[row] = v;
        }
        __syncthreads();

        if (tid == 0) {
            __threadfence();
            unsigned long long tk = atomicAdd(&g_bar_cnt, 1ULL);
            if (t == 0) base = (tk / TOTAL) * TOTAL;
            const unsigned long long target =
                base + (unsigned long long)(t + 1) * RNN_NB;
            while (*(volatile unsigned long long*)&g_bar_cnt < target) { }
            __threadfence();
        }
        __syncthreads();
    }
}

// ===========================================================================
// Logits GEMM via warp-level bf16 mma.sync (HMMA), hi/lo split (3 products).
// C[2048,50257] = hs @ W_out^T + b_out.
// CTA tile 128x128, BK=32, 8 warps (2x4), warp tile 64x32.
// Smem: 80B row pitch (conflict-free ldmatrix), double-buffered, register
// prefetch of next chunk's global loads overlapped with MMA.
// ===========================================================================
#define TCB_M 128
#define TCB_N 128
#define TCB_K 32
#define NCH   (HIDDEN / TCB_K)            // 32
#define PITCH 80                          // 64B data + 16B pad per 32-elem row
#define MATB  (TCB_M * PITCH)             // 10240 bytes per matrix tile
#define BUFB  (4 * MATB)                  // AH, AL, BH, BL
#define MMA_SMEM (2 * BUFB + 512)         // + bias staging

__global__ __launch_bounds__(256, 1)
void mma_logits_kernel(const float* __restrict__ A,    // hs    [2048,1024]
                       const float* __restrict__ B,    // W_out [50257,1024]
                       const float* __restrict__ bias, // [50257]
                       float* __restrict__ C)          // [2048,50257]
{
    extern __shared__ char sm[];
    float* bias_s = (float*)(sm + 2 * BUFB);
    const uint32_t sbase = smem_u32(sm);

    const int tid   = threadIdx.x;
    const int wid   = tid >> 5;
    const int lane  = tid & 31;
    const int warpm = wid >> 2;            // 0..1 -> 64-row slab
    const int warpn = wid & 3;             // 0..3 -> 32-col slab
    const int row0  = blockIdx.x * TCB_M;
    const int col0  = blockIdx.y * TCB_N;

    if (tid < TCB_N) {
        int c = col0 + tid;
        bias_s[tid] = (c < VOCAB) ? bias[c] : 0.0f;
    }

    const float* Abase = A + (size_t)row0 * HIDDEN;
    const float* Bbase = B + (size_t)col0 * HIDDEN;

    float acc[4][4][4];
#pragma unroll
    for (int i = 0; i < 4; i++)
#pragma unroll
        for (int j = 0; j < 4; j++)
#pragma unroll
            for (int r = 0; r < 4; r++) acc[i][j][r] = 0.0f;

    float4 aR[4], bR[4];

    auto ldg_chunk = [&](int k) {
        const int k0 = k * TCB_K;
#pragma unroll
        for (int i = 0; i < 4; i++) {
            int lin = tid + 256 * i;
            int r = lin >> 3, c4 = lin & 7;
            aR[i] = *(const float4*)(Abase + (size_t)r * HIDDEN + k0 + c4 * 4);
            if (col0 + r < VOCAB)
                bR[i] = *(const float4*)(Bbase + (size_t)r * HIDDEN + k0 + c4 * 4);
            else
                bR[i] = make_float4(0.f, 0.f, 0.f, 0.f);
        }
    };

    auto sts_chunk = [&](int buf) {
        char* base = sm + buf * BUFB;
#pragma unroll
        for (int i = 0; i < 4; i++) {
            int lin = tid + 256 * i;
            int r = lin >> 3, c4 = lin & 7;
            int off = r * PITCH + c4 * 8;
            uint2 hi, lo;
            split4(aR[i], hi, lo);
            *(uint2*)(base + off)        = hi;
            *(uint2*)(base + MATB + off) = lo;
            split4(bR[i], hi, lo);
            *(uint2*)(base + 2 * MATB + off) = hi;
            *(uint2*)(base + 3 * MATB + off) = lo;
        }
    };

    auto mma_chunk = [&](int buf) {
        const uint32_t base = sbase + buf * BUFB;
        const uint32_t lrow = lane & 15;
        const uint32_t lhalf = (lane >> 4) * 16;
#pragma unroll
        for (int s = 0; s < 2; s++) {
            uint32_t ah[4][4], al[4][4], bh[2][4], bl[2][4];
#pragma unroll
            for (int mf = 0; mf < 4; mf++) {
                uint32_t ad = base + (warpm * 64 + mf * 16 + lrow) * PITCH
                            + s * 32 + lhalf;
                LDSM_X4(ah[mf][0], ah[mf][1], ah[mf][2], ah[mf][3], ad);
                LDSM_X4(al[mf][0], al[mf][1], al[mf][2], al[mf][3], ad + MATB);
            }
#pragma unroll
            for (int p = 0; p < 2; p++) {
                uint32_t bd = base + 2 * MATB
                            + (warpn * 32 + p * 16 + lrow) * PITCH
                            + s * 32 + lhalf;
                LDSM_X4(bh[p][0], bh[p][1], bh[p][2], bh[p][3], bd);
                LDSM_X4(bl[p][0], bl[p][1], bl[p][2], bl[p][3], bd + MATB);
            }
#pragma unroll
            for (int mf = 0; mf < 4; mf++) {
#pragma unroll
                for (int nf = 0; nf < 4; nf++) {
                    const int p = nf >> 1, q = nf & 1;
                    uint32_t b0h = bh[p][q], b1h = bh[p][q + 2];
                    uint32_t b0l = bl[p][q], b1l = bl[p][q + 2];
                    MMA_BF16(acc[mf][nf], ah[mf][0], ah[mf][1], ah[mf][2], ah[mf][3], b0h, b1h);
                    MMA_BF16(acc[mf][nf], al[mf][0], al[mf][1], al[mf][2], al[mf][3], b0h, b1h);
                    MMA_BF16(acc[mf][nf], ah[mf][0], ah[mf][1], ah[mf][2], ah[mf][3], b0l, b1l);
                }
            }
        }
    };

    ldg_chunk(0);
    sts_chunk(0);
    __syncthreads();

#pragma unroll 1
    for (int k = 0; k < NCH; k++) {
        if (k + 1 < NCH) ldg_chunk(k + 1);     // LDG overlapped with MMA
        mma_chunk(k & 1);
        if (k + 1 < NCH) sts_chunk((k + 1) & 1);
        __syncthreads();
    }

    // epilogue: acc frag layout m16n8 -> (row = lane/4 [+8], col = 2*(lane%4)+{0,1})
#pragma unroll
    for (int mf = 0; mf < 4; mf++) {
#pragma unroll
        for (int nf = 0; nf < 4; nf++) {
            const int mrow = row0 + warpm * 64 + mf * 16 + (lane >> 2);
            const int ncl  = warpn * 32 + nf * 8 + (lane & 3) * 2;
            const int col  = col0 + ncl;
            float* C0 = C + (size_t)mrow * VOCAB;
            float* C1 = C + (size_t)(mrow + 8) * VOCAB;
            if (col < VOCAB) {
                const float bv = bias_s[ncl];
                C0[col] = acc[mf][nf][0] + bv;
                C1[col] = acc[mf][nf][2] + bv;
            }
            if (col + 1 < VOCAB) {
                const float bv = bias_s[ncl + 1];
                C0[col + 1] = acc[mf][nf][1] + bv;
                C1[col + 1] = acc[mf][nf][3] + bv;
            }
        }
    }
}

// ===========================================================================
// launch
// ===========================================================================
extern "C" void kernel_launch(void* const* d_in, const int* in_sizes, int n_in,
                              void* d_out, int out_size)
{
    const int*   x     = (const int*)  d_in[0];
    const float* emb   = (const float*)d_in[1];
    const float* W_xh  = (const float*)d_in[2];
    const float* W_hh  = (const float*)d_in[3];
    const float* b_hh  = (const float*)d_in[4];
    const float* W_out = (const float*)d_in[5];
    const float* b_out = (const float*)d_in[6];

    float* logits  = (float*)d_out;
    float* h_final = (float*)d_out + (size_t)TSTEPS * VOCAB;

    float* xp = nullptr;
    float* hs = nullptr;
    cudaGetSymbolAddress((void**)&xp, g_xp);
    cudaGetSymbolAddress((void**)&hs, g_hs);

    // 1) xp = emb[x] @ W_xh^T      (M=2048, N=1024, K=512)
    {
        dim3 grid(HIDDEN / 128, TSTEPS / 128);
        sgemm_nt_kernel<true><<<grid, 256>>>(emb, W_xh, nullptr, xp, x,
                                             TSTEPS, HIDDEN, EMBED);
    }

    // 2) sequential recurrence -> hs, h_final
    rnn_recurrence_kernel<<<RNN_NB, RNN_NT>>>(xp, W_hh, b_hh, hs, h_final);

    // 3) logits = hs @ W_out^T + b_out  via bf16 mma.sync hi/lo split
    {
        cudaFuncSetAttribute(mma_logits_kernel,
                             cudaFuncAttributeMaxDynamicSharedMemorySize,
                             MMA_SMEM);
        dim3 grid(TSTEPS / TCB_M, (VOCAB + TCB_N - 1) / TCB_N); // 16 x 393
        mma_logits_kernel<<<grid, 256, MMA_SMEM>>>(hs, W_out, b_out, logits);
    }
}